// round 1
// baseline (speedup 1.0000x reference)
#include <cuda_runtime.h>
#include <math.h>

#define E_   128
#define D_   256
#define H_   8
#define DH_  32
#define PTS_ 3
#define N_   384
#define NL_  4
#define NP_  4

// ---------------- device scratch (no allocations allowed) ----------------
__device__ float g_qkbuf[E_ * D_];
__device__ float g_qkout[E_ * 512];     // q cols 0-255, k cols 256-511
__device__ float g_v[E_ * D_];
__device__ float g_x[E_ * D_];          // after norm2
__device__ float g_cat[N_ * 640];       // [qfeat(256) | pe(384)]
__device__ float g_nq[N_ * D_];
__device__ float g_off[N_ * D_];
__device__ float g_attwraw[N_ * 128];
__device__ float g_aw[N_ * 128];
__device__ float g_loc[N_ * D_];
__device__ float g_ref[N_ * 2];
__device__ int   g_lx[N_ * 4];
__device__ int   g_ly[N_ * 4];
__device__ float g_agg[N_ * 2048];      // per (n, h): 256 aggregated src dims
__device__ float g_csum[N_ * 8];
__device__ float g_out256[N_ * D_];
__device__ float g_ca[N_ * D_];
__device__ float g_x2[E_ * D_];
__device__ float g_hid[E_ * 1024];
__device__ float g_ffn[E_ * D_];

// ---------------- helpers ----------------
__device__ __forceinline__ float warp_sum(float v) {
#pragma unroll
    for (int o = 16; o; o >>= 1) v += __shfl_xor_sync(0xffffffffu, v, o);
    return v;
}
__device__ __forceinline__ float warp_max(float v) {
#pragma unroll
    for (int o = 16; o; o >>= 1) v = fmaxf(v, __shfl_xor_sync(0xffffffffu, v, o));
    return v;
}

// block-wide layernorm over 256 values (one per thread), 256 threads
__device__ __forceinline__ float block_ln256(float y, const float* w, const float* b, int t) {
    __shared__ float red[8];
    int lane = t & 31, wp = t >> 5;
    float s = warp_sum(y);
    if (lane == 0) red[wp] = s;
    __syncthreads();
    float tot = 0.f;
#pragma unroll
    for (int i = 0; i < 8; i++) tot += red[i];
    float mean = tot * (1.0f / 256.0f);
    __syncthreads();
    float dev = y - mean;
    float s2 = warp_sum(dev * dev);
    if (lane == 0) red[wp] = s2;
    __syncthreads();
    float tot2 = 0.f;
#pragma unroll
    for (int i = 0; i < 8; i++) tot2 += red[i];
    float var = tot2 * (1.0f / 256.0f);
    return dev * rsqrtf(var + 1e-5f) * w[t] + b[t];
}

// ---------------- generic tiled GEMM: C[M,O] = A[M,K] @ W[O,K]^T + bias, opt relu ----
// M % 64 == 0, O % 64 == 0, K % 16 == 0. grid = (O/64, M/64), 256 threads.
__global__ void k_gemm(const float* __restrict__ A, const float* __restrict__ W,
                       const float* __restrict__ bias, float* __restrict__ C,
                       int M, int O, int K, int relu) {
    __shared__ float As[64][17];
    __shared__ float Ws[64][17];
    int t  = threadIdx.x;
    int tx = t & 15, ty = t >> 4;
    int m0 = blockIdx.y * 64, o0 = blockIdx.x * 64;
    float acc[4][4];
#pragma unroll
    for (int i = 0; i < 4; i++)
#pragma unroll
        for (int j = 0; j < 4; j++) acc[i][j] = 0.f;

    for (int k0 = 0; k0 < K; k0 += 16) {
#pragma unroll
        for (int i = 0; i < 4; i++) {
            int lin = t + 256 * i;
            int r = lin >> 4, c = lin & 15;
            As[r][c] = A[(size_t)(m0 + r) * K + k0 + c];
            Ws[r][c] = W[(size_t)(o0 + r) * K + k0 + c];
        }
        __syncthreads();
#pragma unroll
        for (int kk = 0; kk < 16; kk++) {
            float a[4], w[4];
#pragma unroll
            for (int i = 0; i < 4; i++) a[i] = As[ty * 4 + i][kk];
#pragma unroll
            for (int j = 0; j < 4; j++) w[j] = Ws[tx * 4 + j][kk];
#pragma unroll
            for (int i = 0; i < 4; i++)
#pragma unroll
                for (int j = 0; j < 4; j++) acc[i][j] += a[i] * w[j];
        }
        __syncthreads();
    }
#pragma unroll
    for (int i = 0; i < 4; i++)
#pragma unroll
        for (int j = 0; j < 4; j++) {
            int m = m0 + ty * 4 + i, o = o0 + tx * 4 + j;
            float v = acc[i][j] + bias[o];
            if (relu) v = fmaxf(v, 0.f);
            C[(size_t)m * O + o] = v;
        }
}

// ---------------- k_prep: qkbuf = tgt + query_pos ----------------
__global__ void k_prep(const float* __restrict__ tgt, const float* __restrict__ qpos) {
    int i = blockIdx.x * 256 + threadIdx.x;
    g_qkbuf[i] = tgt[i] + qpos[i];
}

// ---------------- k_attn: self-attn + out-proj + residual + norm2 -> g_x --------
__global__ void k_attn(const float* __restrict__ wo, const float* __restrict__ bo,
                       const float* __restrict__ tgt,
                       const float* __restrict__ n2w, const float* __restrict__ n2b) {
    int e = blockIdx.x, t = threadIdx.x;
    __shared__ float sq[256];
    __shared__ float sc[1024];
    __shared__ __align__(16) float so[256];
    sq[t] = g_qkout[e * 512 + t];
    __syncthreads();
    const float scale = 0.17677669529663687f; // 32^-0.5
#pragma unroll
    for (int i = 0; i < 4; i++) {
        int idx = t + 256 * i;
        int h = idx >> 7, f = idx & 127;
        const float* kr = g_qkout + f * 512 + 256 + h * 32;
        const float* qr = sq + h * 32;
        float s = 0.f;
#pragma unroll
        for (int d = 0; d < 32; d++) s += qr[d] * kr[d];
        sc[idx] = s * scale;
    }
    __syncthreads();
    // softmax per head (warp h handles head h; 4 values per lane)
    {
        int wp = t >> 5, lane = t & 31;
        float vals[4];
        float m = -1e30f;
#pragma unroll
        for (int i = 0; i < 4; i++) { vals[i] = sc[wp * 128 + lane + 32 * i]; m = fmaxf(m, vals[i]); }
        m = warp_max(m);
        float sum = 0.f;
#pragma unroll
        for (int i = 0; i < 4; i++) { vals[i] = expf(vals[i] - m); sum += vals[i]; }
        sum = warp_sum(sum);
        float inv = 1.0f / sum;
#pragma unroll
        for (int i = 0; i < 4; i++) sc[wp * 128 + lane + 32 * i] = vals[i] * inv;
    }
    __syncthreads();
    // out[h,d] = sum_f att * v
    {
        int h = t >> 5;
        float acc = 0.f;
        for (int f = 0; f < 128; f++) acc += sc[h * 128 + f] * g_v[f * 256 + t];
        so[t] = acc;
    }
    __syncthreads();
    // out-proj + residual
    float y = bo[t] + tgt[e * 256 + t];
    {
        const float4* wr = (const float4*)(wo + (size_t)t * 256);
        const float4* sp = (const float4*)so;
#pragma unroll 8
        for (int u = 0; u < 64; u++) {
            float4 w4 = wr[u];
            float4 s4 = sp[u];
            y += w4.x * s4.x + w4.y * s4.y + w4.z * s4.z + w4.w * s4.w;
        }
    }
    g_x[e * 256 + t] = block_ln256(y, n2w, n2b, t);
}

// ---------------- k_geom: geometry + positional encoding ----------------
__global__ void k_geom(const float* __restrict__ edge) {
    int n = blockIdx.x * 128 + threadIdx.x;
    if (n >= N_) return;
    int e = n / 3, p = n % 3;
    float ax = edge[e * 4 + 0], ay = edge[e * 4 + 1];
    float bx = edge[e * 4 + 2], by = edge[e * 4 + 3];
    float tpar = (float)p / 2.0f;
    float ptx = ax + tpar * (bx - ax);
    float pty = ay + tpar * (by - ay);
    float cxf = floorf(ptx), cyf = floorf(pty);
    int icx = (int)cxf, icy = (int)cyf;
    int minx = max(icx - 128, 0); if (minx + 256 > 2048) minx = 1792;
    int miny = max(icy - 128, 0); if (miny + 256 > 2048) miny = 1792;
    float fminx = (float)minx, fminy = (float)miny;
    float dx = bx - ax, dy = by - ay;

    float tlx, thx, tly, thy;
    {
        float safe = (dx == 0.f) ? 1.f : dx;
        float t1 = (fminx - ax) / safe, t2 = (fminx + 256.f - ax) / safe;
        tlx = (dx == 0.f) ? 0.f : fminf(t1, t2);
        thx = (dx == 0.f) ? 1.f : fmaxf(t1, t2);
    }
    {
        float safe = (dy == 0.f) ? 1.f : dy;
        float t1 = (fminy - ay) / safe, t2 = (fminy + 256.f - ay) / safe;
        tly = (dy == 0.f) ? 0.f : fminf(t1, t2);
        thy = (dy == 0.f) ? 1.f : fmaxf(t1, t2);
    }
    float t0 = fmaxf(fmaxf(tlx, tly), 0.f);
    float t1v = fmaxf(fminf(fminf(thx, thy), 1.f), t0);
    float cax = ax + t0 * dx, cay = ay + t0 * dy;
    float cbx = ax + t1v * dx, cby = ay + t1v * dy;

    float posx[3] = {cax, cbx, (float)icx};
    float posy[3] = {cay, cby, (float)icy};
    float* pe = g_cat + (size_t)n * 640 + 256;
    for (int k = 0; k < 32; k++) {
        float T = (float)pow(10000.0, (double)k / 32.0);
#pragma unroll
        for (int comp = 0; comp < 3; comp++) {
            float sy, cy2, sx, cx2;
            sincosf(posy[comp] / T, &sy, &cy2);
            sincosf(posx[comp] / T, &sx, &cx2);
            pe[comp * 128 + 2 * k]      = sy;
            pe[comp * 128 + 2 * k + 1]  = cy2;
            pe[comp * 128 + 64 + 2 * k]     = sx;
            pe[comp * 128 + 64 + 2 * k + 1] = cx2;
        }
    }
    g_ref[n * 2 + 0] = ((float)icx - fminx) / 256.f;
    g_ref[n * 2 + 1] = ((float)icy - fminy) / 256.f;
    const float ratio[4] = {8.f, 16.f, 32.f, 64.f};
#pragma unroll
    for (int l = 0; l < 4; l++) {
        g_lx[n * 4 + l] = (int)rintf(fminx / ratio[l]);
        g_ly[n * 4 + l] = (int)rintf(fminy / ratio[l]);
    }
}

// ---------------- k_catq: g_cat[:,0:256] = x[e] + query_pos[e] ----------------
__global__ void k_catq(const float* __restrict__ qpos) {
    int n = blockIdx.x, t = threadIdx.x;
    int e = n / 3;
    g_cat[(size_t)n * 640 + t] = g_x[e * 256 + t] + qpos[e * 256 + t];
}

// ---------------- k_locaw: attention-weight softmax + sampling locations ------
__global__ void k_locaw(const float* __restrict__ vr) {
    int n = blockIdx.x, t = threadIdx.x;
    __shared__ float sat[128];
    __shared__ float mh[8], sh[8];
    if (t < 128) sat[t] = g_attwraw[n * 128 + t];
    __syncthreads();
    if (t < 8) {
        float m = -1e30f;
        for (int i = 0; i < 16; i++) m = fmaxf(m, sat[t * 16 + i]);
        float s = 0.f;
        for (int i = 0; i < 16; i++) s += expf(sat[t * 16 + i] - m);
        mh[t] = m; sh[t] = s;
    }
    __syncthreads();
    if (t < 128) {
        int h = t >> 4;
        g_aw[n * 128 + t] = expf(sat[t] - mh[h]) / sh[h];
    }
    {
        const float slen[4] = {32.f, 16.f, 8.f, 4.f};
        int l = (t >> 3) & 3, xy = t & 1;
        float off = g_off[n * 256 + t];
        g_loc[n * 256 + t] = g_ref[n * 2 + xy] * vr[l * 2 + xy] + off / slen[l];
    }
}

// ---------------- k_sample: gather taps, aggregate weighted src rows ----------
__global__ void k_sample(const float* __restrict__ src, const unsigned char* __restrict__ msk) {
    int n = blockIdx.x;
    int h = threadIdx.x >> 5, lane = threadIdx.x & 31;
    float agg[8];
#pragma unroll
    for (int k = 0; k < 8; k++) agg[k] = 0.f;
    float csum = 0.f;
    const float* loc = g_loc + (size_t)n * 256 + h * 32;
    const float* aw  = g_aw + (size_t)n * 128 + h * 16;
    const int s_arr[4]   = {32, 16, 8, 4};
    const int w_arr[4]   = {256, 128, 64, 32};
    const int st_arr[4]  = {0, 65536, 81920, 86016};
#pragma unroll
    for (int l = 0; l < 4; l++) {
        int s = s_arr[l], W = w_arr[l], base = st_arr[l];
        int lxl = g_lx[n * 4 + l], lyl = g_ly[n * 4 + l];
#pragma unroll
        for (int p = 0; p < 4; p++) {
            float gx = loc[l * 8 + p * 2 + 0];
            float gy = loc[l * 8 + p * 2 + 1];
            float a = aw[l * 4 + p];
            float px = gx * (float)s - 0.5f;
            float py = gy * (float)s - 0.5f;
            float fx0 = floorf(px), fy0 = floorf(py);
            int x0 = (int)fx0, y0 = (int)fy0;
            float fx = px - fx0, fy = py - fy0;
            float wts[4] = {(1.f - fx) * (1.f - fy), fx * (1.f - fy),
                            (1.f - fx) * fy, fx * fy};
            int xs[4] = {x0, x0 + 1, x0, x0 + 1};
            int ys[4] = {y0, y0, y0 + 1, y0 + 1};
#pragma unroll
            for (int tp = 0; tp < 4; tp++) {
                int xi = xs[tp], yi = ys[tp];
                if (xi < 0 || xi >= s || yi < 0 || yi >= s) continue;
                int pix = base + (lyl + yi) * W + (lxl + xi);
                if (msk[pix]) continue;
                float c = a * wts[tp];
                csum += c;
                const float* row = src + (size_t)pix * 256 + lane;
#pragma unroll
                for (int k = 0; k < 8; k++) agg[k] += c * __ldg(row + 32 * k);
            }
        }
    }
    float* out = g_agg + (size_t)n * 2048 + h * 256 + lane;
#pragma unroll
    for (int k = 0; k < 8; k++) out[32 * k] = agg[k];
    if (lane == 0) g_csum[n * 8 + h] = csum;
}

// ---------------- k_headgemm: out256[n, h*32+j] = valW_h @ agg + csum*val_b ----
// grid (N/64, 8), 256 threads
__global__ void k_headgemm(const float* __restrict__ valw, const float* __restrict__ valb) {
    __shared__ float sw[32 * 257];
    int t = threadIdx.x;
    int h = blockIdx.y;
    int n0 = blockIdx.x * 64;
    for (int i = 0; i < 32; i++) {
        int idx = t + 256 * i;
        int r = idx >> 8, c = idx & 255;
        sw[r * 257 + c] = valw[(size_t)(h * 32 + r) * 256 + c];
    }
    __syncthreads();
    int j = t & 31, nb = t >> 5;
    float vb = valb[h * 32 + j];
#pragma unroll
    for (int i = 0; i < 8; i++) {
        int n = n0 + nb + 8 * i;
        const float* arow = g_agg + (size_t)n * 2048 + h * 256;
        float acc = 0.f;
#pragma unroll 8
        for (int d = 0; d < 256; d++) acc += arow[d] * sw[j * 257 + d];
        g_out256[(size_t)n * 256 + h * 32 + j] = acc + g_csum[n * 8 + h] * vb;
    }
}

// ---------------- k_pool_ln: pooled mean over PTS + residual + norm1 -> g_x2 ---
__global__ void k_pool_ln(const float* __restrict__ n1w, const float* __restrict__ n1b) {
    int e = blockIdx.x, t = threadIdx.x;
    float pooled = (g_ca[(3 * e + 0) * 256 + t] + g_ca[(3 * e + 1) * 256 + t] +
                    g_ca[(3 * e + 2) * 256 + t]) / 3.0f;
    float y = g_x[e * 256 + t] + pooled;
    g_x2[e * 256 + t] = block_ln256(y, n1w, n1b, t);
}

// ---------------- k_final_ln: residual + norm3 -> d_out ----------------
__global__ void k_final_ln(const float* __restrict__ n3w, const float* __restrict__ n3b,
                           float* __restrict__ out) {
    int e = blockIdx.x, t = threadIdx.x;
    float y = g_x2[e * 256 + t] + g_ffn[e * 256 + t];
    out[e * 256 + t] = block_ln256(y, n3w, n3b, t);
}

// ---------------- launch ----------------
extern "C" void kernel_launch(void* const* d_in, const int* in_sizes, int n_in,
                              void* d_out, int out_size) {
    const float* tgt      = (const float*)d_in[0];
    const float* qpos     = (const float*)d_in[1];
    const float* edge     = (const float*)d_in[2];
    const float* src      = (const float*)d_in[3];
    const unsigned char* msk = (const unsigned char*)d_in[4];
    const float* vr       = (const float*)d_in[5];
    const float* inw      = (const float*)d_in[6];
    const float* inb      = (const float*)d_in[7];
    const float* ow       = (const float*)d_in[8];
    const float* ob       = (const float*)d_in[9];
    const float* n1w      = (const float*)d_in[10];
    const float* n1b      = (const float*)d_in[11];
    const float* n2w      = (const float*)d_in[12];
    const float* n2b      = (const float*)d_in[13];
    const float* n3w      = (const float*)d_in[14];
    const float* n3b      = (const float*)d_in[15];
    const float* l0w      = (const float*)d_in[16];
    const float* l0b      = (const float*)d_in[17];
    const float* l1w      = (const float*)d_in[18];
    const float* l1b      = (const float*)d_in[19];
    const float* l2w      = (const float*)d_in[20];
    const float* l2b      = (const float*)d_in[21];
    const float* offw     = (const float*)d_in[22];
    const float* offb     = (const float*)d_in[23];
    const float* attww    = (const float*)d_in[24];
    const float* attwb    = (const float*)d_in[25];
    const float* valw     = (const float*)d_in[26];
    const float* valb     = (const float*)d_in[27];
    const float* oprojw   = (const float*)d_in[28];
    const float* oprojb   = (const float*)d_in[29];
    float* out = (float*)d_out;

    float *gqkbuf, *gqkout, *gv, *gcat, *gnq, *goff, *gattw, *gout256, *gca, *gx2, *ghid, *gffn;
    cudaGetSymbolAddress((void**)&gqkbuf, g_qkbuf);
    cudaGetSymbolAddress((void**)&gqkout, g_qkout);
    cudaGetSymbolAddress((void**)&gv, g_v);
    cudaGetSymbolAddress((void**)&gcat, g_cat);
    cudaGetSymbolAddress((void**)&gnq, g_nq);
    cudaGetSymbolAddress((void**)&goff, g_off);
    cudaGetSymbolAddress((void**)&gattw, g_attwraw);
    cudaGetSymbolAddress((void**)&gout256, g_out256);
    cudaGetSymbolAddress((void**)&gca, g_ca);
    cudaGetSymbolAddress((void**)&gx2, g_x2);
    cudaGetSymbolAddress((void**)&ghid, g_hid);
    cudaGetSymbolAddress((void**)&gffn, g_ffn);

    // geometry (independent of attention) first
    k_geom<<<3, 128>>>(edge);
    // qk buffer and projections
    k_prep<<<128, 256>>>(tgt, qpos);
    k_gemm<<<dim3(8, 2), 256>>>(gqkbuf, inw, inb, gqkout, 128, 512, 256, 0);
    k_gemm<<<dim3(4, 2), 256>>>(tgt, inw + 512 * 256, inb + 512, gv, 128, 256, 256, 0);
    // attention + out-proj + norm2
    k_attn<<<128, 256>>>(ow, ob, tgt, n2w, n2b);
    // build concat features, lin0
    k_catq<<<384, 256>>>(qpos);
    k_gemm<<<dim3(4, 6), 256>>>(gcat, l0w, l0b, gnq, 384, 256, 640, 0);
    // offsets + attention weights
    k_gemm<<<dim3(4, 6), 256>>>(gnq, offw, offb, goff, 384, 256, 256, 0);
    k_gemm<<<dim3(2, 6), 256>>>(gnq, attww, attwb, gattw, 384, 128, 256, 0);
    k_locaw<<<384, 256>>>(vr);
    // deformable sampling (aggregated src rows)
    k_sample<<<384, 256>>>(src, msk);
    k_headgemm<<<dim3(6, 8), 256>>>(valw, valb);
    k_gemm<<<dim3(4, 6), 256>>>(gout256, oprojw, oprojb, gca, 384, 256, 256, 0);
    // pool + norm1
    k_pool_ln<<<128, 256>>>(n1w, n1b);
    // FFN
    k_gemm<<<dim3(16, 2), 256>>>(gx2, l1w, l1b, ghid, 128, 1024, 256, 1);
    k_gemm<<<dim3(4, 2), 256>>>(ghid, l2w, l2b, gffn, 128, 256, 1024, 0);
    // final norm3 -> output
    k_final_ln<<<128, 256>>>(n3w, n3b, out);
}

// round 2
// speedup vs baseline: 1.7482x; 1.7482x over previous
#include <cuda_runtime.h>
#include <math.h>

typedef unsigned long long ull;

#define E_   128
#define N_   384

// ---------------- device scratch ----------------
__device__ float g_qkout[E_ * 768];     // q | k | v
__device__ float g_x[E_ * 256];         // after norm2
__device__ float g_pe[N_ * 384];        // positional encoding
__device__ float g_nq[N_ * 256];
__device__ float g_offatt[N_ * 384];    // off(256) | attw raw(128)
__device__ float g_ref[N_ * 2];
__device__ int   g_lx[N_ * 4];
__device__ int   g_ly[N_ * 4];
__device__ float g_agg[N_ * 2048];
__device__ float g_csum[N_ * 8];
__device__ float g_out256[N_ * 256];
__device__ float g_ca[N_ * 256];
__device__ float g_x2[E_ * 256];
__device__ float g_hid[E_ * 1024];
__device__ float g_ffn[E_ * 256];

// ---------------- f32x2 helpers ----------------
__device__ __forceinline__ ull pack2(float lo, float hi) {
    ull r;
    asm("mov.b64 %0, {%1, %2};" : "=l"(r)
        : "r"(__float_as_uint(lo)), "r"(__float_as_uint(hi)));
    return r;
}
__device__ __forceinline__ void fma2(ull& d, ull a, ull b) {
    asm("fma.rn.f32x2 %0, %1, %2, %0;" : "+l"(d) : "l"(a), "l"(b));
}
__device__ __forceinline__ float2 unpack2(ull v) {
    unsigned lo, hi;
    asm("mov.b64 {%0, %1}, %2;" : "=r"(lo), "=r"(hi) : "l"(v));
    return make_float2(__uint_as_float(lo), __uint_as_float(hi));
}

__device__ __forceinline__ float warp_sum(float v) {
#pragma unroll
    for (int o = 16; o; o >>= 1) v += __shfl_xor_sync(0xffffffffu, v, o);
    return v;
}
__device__ __forceinline__ float warp_max(float v) {
#pragma unroll
    for (int o = 16; o; o >>= 1) v = fmaxf(v, __shfl_xor_sync(0xffffffffu, v, o));
    return v;
}

__device__ __forceinline__ float block_ln256(float y, const float* w, const float* b, int t) {
    __shared__ float red[8];
    int lane = t & 31, wp = t >> 5;
    float s = warp_sum(y);
    if (lane == 0) red[wp] = s;
    __syncthreads();
    float tot = 0.f;
#pragma unroll
    for (int i = 0; i < 8; i++) tot += red[i];
    float mean = tot * (1.0f / 256.0f);
    __syncthreads();
    float dev = y - mean;
    float s2 = warp_sum(dev * dev);
    if (lane == 0) red[wp] = s2;
    __syncthreads();
    float tot2 = 0.f;
#pragma unroll
    for (int i = 0; i < 8; i++) tot2 += red[i];
    float var = tot2 * (1.0f / 256.0f);
    return dev * rsqrtf(var + 1e-5f) * w[t] + b[t];
}

// ================= fused GEMM =================
// C[M,O] = A'[M,K] @ Wsel[O,K]^T + bias, tiles 32(M)x64(O), K-tile 32,
// 256 threads, thread computes 2x4 via f32x2 (o-pair packed).
// amode 0: A' = A
// amode 1: A' = A (+ A2 when o0 < a2lim)        [qkv fused prep]
// amode 2: A'[m,k] = k<256 ? g_x[m/3]+A2[m/3] : g_pe[m]   [lin0 fused cat]
// W select: o >= o_split (if o_split>0) -> W2 row (o-o_split), bias2.
__global__ __launch_bounds__(256) void k_gemm2(
    const float* __restrict__ A, const float* __restrict__ A2,
    const float* __restrict__ W, const float* __restrict__ W2,
    const float* __restrict__ bias, const float* __restrict__ bias2,
    float* __restrict__ C, int M, int O, int K,
    int o_split, int a2lim, int amode, int relu)
{
    __shared__ float As[2 * 32 * 33];   // m-major, pad 33
    __shared__ float Ws[2 * 32 * 68];   // kk-major, pad 68
    int t = threadIdx.x;
    int tx = t & 15, ty = t >> 4;
    int m0 = blockIdx.y * 32, o0 = blockIdx.x * 64;

    // A load mapping: row = t>>3 (0..31), col4 = (t&7)*4
    int ar = t >> 3, ac = (t & 7) * 4;
    // W load mapping: o row = t&63, k col8 = (t>>6)*8
    int wr = t & 63, wc = (t >> 6) * 8;

    bool addA2 = (amode == 1) && (o0 < a2lim);
    int orow = o0 + wr;
    const float* Wrow = (o_split > 0 && orow >= o_split)
                        ? (W2 + (size_t)(orow - o_split) * K)
                        : (W + (size_t)orow * K);

    ull acc2[2][2];
#pragma unroll
    for (int i = 0; i < 2; i++)
#pragma unroll
        for (int j = 0; j < 2; j++) acc2[i][j] = pack2(0.f, 0.f);

    int nk = K >> 5;
    float4 pa, pw0, pw1;

    auto fetch = [&](int kt) {
        int kgA = kt * 32 + ac;
        int m = m0 + ar;
        if (amode == 2) {
            if (kgA < 256) {
                int e = m / 3;
                float4 x = *(const float4*)(A + (size_t)e * 256 + kgA);
                float4 q = *(const float4*)(A2 + (size_t)e * 256 + kgA);
                pa = make_float4(x.x + q.x, x.y + q.y, x.z + q.z, x.w + q.w);
            } else {
                pa = *(const float4*)(g_pe + (size_t)m * 384 + (kgA - 256));
            }
        } else {
            float4 x = *(const float4*)(A + (size_t)m * K + kgA);
            if (addA2) {
                float4 q = *(const float4*)(A2 + (size_t)m * K + kgA);
                x = make_float4(x.x + q.x, x.y + q.y, x.z + q.z, x.w + q.w);
            }
            pa = x;
        }
        int kgW = kt * 32 + wc;
        pw0 = *(const float4*)(Wrow + kgW);
        pw1 = *(const float4*)(Wrow + kgW + 4);
    };
    auto store = [&](int s) {
        float* as = As + s * (32 * 33);
        float* ws = Ws + s * (32 * 68);
        as[ar * 33 + ac + 0] = pa.x;
        as[ar * 33 + ac + 1] = pa.y;
        as[ar * 33 + ac + 2] = pa.z;
        as[ar * 33 + ac + 3] = pa.w;
        ws[(wc + 0) * 68 + wr] = pw0.x;
        ws[(wc + 1) * 68 + wr] = pw0.y;
        ws[(wc + 2) * 68 + wr] = pw0.z;
        ws[(wc + 3) * 68 + wr] = pw0.w;
        ws[(wc + 4) * 68 + wr] = pw1.x;
        ws[(wc + 5) * 68 + wr] = pw1.y;
        ws[(wc + 6) * 68 + wr] = pw1.z;
        ws[(wc + 7) * 68 + wr] = pw1.w;
    };

    fetch(0);
    store(0);
    __syncthreads();
    for (int kt = 0; kt < nk; kt++) {
        int s = kt & 1;
        if (kt + 1 < nk) fetch(kt + 1);
        const float* as = As + s * (32 * 33);
        const float* ws = Ws + s * (32 * 68);
#pragma unroll
        for (int kk = 0; kk < 32; kk++) {
            float a0 = as[(ty * 2 + 0) * 33 + kk];
            float a1 = as[(ty * 2 + 1) * 33 + kk];
            ull a0p = pack2(a0, a0);
            ull a1p = pack2(a1, a1);
            ull w01 = *(const ull*)(ws + kk * 68 + tx * 4);
            ull w23 = *(const ull*)(ws + kk * 68 + tx * 4 + 2);
            fma2(acc2[0][0], a0p, w01);
            fma2(acc2[0][1], a0p, w23);
            fma2(acc2[1][0], a1p, w01);
            fma2(acc2[1][1], a1p, w23);
        }
        if (kt + 1 < nk) {
            __syncthreads();
            store(s ^ 1);
            __syncthreads();
        }
    }

#pragma unroll
    for (int i = 0; i < 2; i++) {
        float2 p0 = unpack2(acc2[i][0]);
        float2 p1 = unpack2(acc2[i][1]);
        float vals[4] = {p0.x, p0.y, p1.x, p1.y};
        int m = m0 + ty * 2 + i;
#pragma unroll
        for (int j = 0; j < 4; j++) {
            int o = o0 + tx * 4 + j;
            float b = (o_split > 0 && o >= o_split) ? bias2[o - o_split] : bias[o];
            float v = vals[j] + b;
            if (relu) v = fmaxf(v, 0.f);
            C[(size_t)m * O + o] = v;
        }
    }
}

// ================= self-attn + out-proj + residual + norm2 =================
__global__ __launch_bounds__(256) void k_attn(
    const float* __restrict__ wo, const float* __restrict__ bo,
    const float* __restrict__ tgt,
    const float* __restrict__ n2w, const float* __restrict__ n2b)
{
    int e = blockIdx.x, t = threadIdx.x;
    __shared__ float sq[256];
    __shared__ float sc[1024];
    __shared__ __align__(16) float so[256];
    sq[t] = g_qkout[e * 768 + t];
    __syncthreads();
    const float scale = 0.17677669529663687f;
#pragma unroll
    for (int i = 0; i < 4; i++) {
        int idx = t + 256 * i;
        int h = idx >> 7, f = idx & 127;
        const float* kr = g_qkout + f * 768 + 256 + h * 32;
        const float* qr = sq + h * 32;
        float s = 0.f;
#pragma unroll
        for (int d = 0; d < 32; d++) s += qr[d] * kr[d];
        sc[idx] = s * scale;
    }
    __syncthreads();
    {
        int wp = t >> 5, lane = t & 31;
        float vals[4];
        float m = -1e30f;
#pragma unroll
        for (int i = 0; i < 4; i++) { vals[i] = sc[wp * 128 + lane + 32 * i]; m = fmaxf(m, vals[i]); }
        m = warp_max(m);
        float sum = 0.f;
#pragma unroll
        for (int i = 0; i < 4; i++) { vals[i] = expf(vals[i] - m); sum += vals[i]; }
        sum = warp_sum(sum);
        float inv = 1.0f / sum;
#pragma unroll
        for (int i = 0; i < 4; i++) sc[wp * 128 + lane + 32 * i] = vals[i] * inv;
    }
    __syncthreads();
    {
        int h = t >> 5;
        float acc = 0.f;
        for (int f = 0; f < 128; f++) acc += sc[h * 128 + f] * g_qkout[f * 768 + 512 + t];
        so[t] = acc;
    }
    __syncthreads();
    float y = bo[t] + tgt[e * 256 + t];
    {
        ull acc2 = pack2(0.f, 0.f);
        const ull* wr2 = (const ull*)(wo + (size_t)t * 256);
        const ull* sp2 = (const ull*)so;
#pragma unroll 16
        for (int u = 0; u < 128; u++) fma2(acc2, wr2[u], sp2[u]);
        float2 r = unpack2(acc2);
        y += r.x + r.y;
    }
    g_x[e * 256 + t] = block_ln256(y, n2w, n2b, t);
}

// ================= geometry + positional encoding =================
__global__ void k_geom(const float* __restrict__ edge) {
    __shared__ float Ts[32];
    if (threadIdx.x < 32)
        Ts[threadIdx.x] = (float)pow(10000.0, (double)threadIdx.x / 32.0);
    __syncthreads();
    int n = blockIdx.x * 128 + threadIdx.x;
    if (n >= N_) return;
    int e = n / 3, p = n % 3;
    float ax = edge[e * 4 + 0], ay = edge[e * 4 + 1];
    float bx = edge[e * 4 + 2], by = edge[e * 4 + 3];
    float tpar = (float)p / 2.0f;
    float ptx = ax + tpar * (bx - ax);
    float pty = ay + tpar * (by - ay);
    float cxf = floorf(ptx), cyf = floorf(pty);
    int icx = (int)cxf, icy = (int)cyf;
    int minx = max(icx - 128, 0); if (minx + 256 > 2048) minx = 1792;
    int miny = max(icy - 128, 0); if (miny + 256 > 2048) miny = 1792;
    float fminx = (float)minx, fminy = (float)miny;
    float dx = bx - ax, dy = by - ay;

    float tlx, thx, tly, thy;
    {
        float safe = (dx == 0.f) ? 1.f : dx;
        float t1 = (fminx - ax) / safe, t2 = (fminx + 256.f - ax) / safe;
        tlx = (dx == 0.f) ? 0.f : fminf(t1, t2);
        thx = (dx == 0.f) ? 1.f : fmaxf(t1, t2);
    }
    {
        float safe = (dy == 0.f) ? 1.f : dy;
        float t1 = (fminy - ay) / safe, t2 = (fminy + 256.f - ay) / safe;
        tly = (dy == 0.f) ? 0.f : fminf(t1, t2);
        thy = (dy == 0.f) ? 1.f : fmaxf(t1, t2);
    }
    float t0 = fmaxf(fmaxf(tlx, tly), 0.f);
    float t1v = fmaxf(fminf(fminf(thx, thy), 1.f), t0);
    float cax = ax + t0 * dx, cay = ay + t0 * dy;
    float cbx = ax + t1v * dx, cby = ay + t1v * dy;

    float posx[3] = {cax, cbx, (float)icx};
    float posy[3] = {cay, cby, (float)icy};
    float* pe = g_pe + (size_t)n * 384;
    for (int k = 0; k < 32; k++) {
        float T = Ts[k];
#pragma unroll
        for (int comp = 0; comp < 3; comp++) {
            float sy, cy2, sx, cx2;
            sincosf(posy[comp] / T, &sy, &cy2);
            sincosf(posx[comp] / T, &sx, &cx2);
            pe[comp * 128 + 2 * k]          = sy;
            pe[comp * 128 + 2 * k + 1]      = cy2;
            pe[comp * 128 + 64 + 2 * k]     = sx;
            pe[comp * 128 + 64 + 2 * k + 1] = cx2;
        }
    }
    g_ref[n * 2 + 0] = ((float)icx - fminx) / 256.f;
    g_ref[n * 2 + 1] = ((float)icy - fminy) / 256.f;
    const float ratio[4] = {8.f, 16.f, 32.f, 64.f};
#pragma unroll
    for (int l = 0; l < 4; l++) {
        g_lx[n * 4 + l] = (int)rintf(fminx / ratio[l]);
        g_ly[n * 4 + l] = (int)rintf(fminy / ratio[l]);
    }
}

// ================= sampling (fused aw-softmax + loc + gather) =================
__global__ __launch_bounds__(256) void k_sample(
    const float* __restrict__ src, const unsigned char* __restrict__ msk,
    const float* __restrict__ vr)
{
    int n = blockIdx.x, t = threadIdx.x;
    __shared__ float sloc[256];
    __shared__ float saw[128];
    __shared__ float mh[8], sh[8];
    if (t < 128) saw[t] = g_offatt[n * 384 + 256 + t];
    // sampling locations
    {
        const float slen[4] = {32.f, 16.f, 8.f, 4.f};
        int l = (t >> 3) & 3, xy = t & 1;
        float off = g_offatt[n * 384 + t];
        sloc[t] = g_ref[n * 2 + xy] * vr[l * 2 + xy] + off / slen[l];
    }
    __syncthreads();
    if (t < 8) {
        float m = -1e30f;
        for (int i = 0; i < 16; i++) m = fmaxf(m, saw[t * 16 + i]);
        float s = 0.f;
        for (int i = 0; i < 16; i++) s += expf(saw[t * 16 + i] - m);
        mh[t] = m; sh[t] = s;
    }
    __syncthreads();
    if (t < 128) {
        int h = t >> 4;
        saw[t] = expf(saw[t] - mh[h]) / sh[h];
    }
    __syncthreads();

    int h = t >> 5, lane = t & 31;
    float4 a0 = make_float4(0.f, 0.f, 0.f, 0.f);
    float4 a1 = make_float4(0.f, 0.f, 0.f, 0.f);
    float csum = 0.f;
    const int s_arr[4]  = {32, 16, 8, 4};
    const int w_arr[4]  = {256, 128, 64, 32};
    const int st_arr[4] = {0, 65536, 81920, 86016};
#pragma unroll
    for (int l = 0; l < 4; l++) {
        int s = s_arr[l], W = w_arr[l], base = st_arr[l];
        int lxl = g_lx[n * 4 + l], lyl = g_ly[n * 4 + l];
#pragma unroll
        for (int p = 0; p < 4; p++) {
            float gx = sloc[h * 32 + l * 8 + p * 2 + 0];
            float gy = sloc[h * 32 + l * 8 + p * 2 + 1];
            float a  = saw[h * 16 + l * 4 + p];
            float px = gx * (float)s - 0.5f;
            float py = gy * (float)s - 0.5f;
            float fx0 = floorf(px), fy0 = floorf(py);
            int x0 = (int)fx0, y0 = (int)fy0;
            float fx = px - fx0, fy = py - fy0;
            float wts[4] = {(1.f - fx) * (1.f - fy), fx * (1.f - fy),
                            (1.f - fx) * fy, fx * fy};
            int xs[4] = {x0, x0 + 1, x0, x0 + 1};
            int ys[4] = {y0, y0, y0 + 1, y0 + 1};
#pragma unroll
            for (int tp = 0; tp < 4; tp++) {
                int xi = xs[tp], yi = ys[tp];
                bool ok = (xi >= 0) & (xi < s) & (yi >= 0) & (yi < s);
                int xc = min(max(xi, 0), s - 1);
                int yc = min(max(yi, 0), s - 1);
                int pix = base + (lyl + yc) * W + (lxl + xc);
                ok = ok && !msk[pix];
                float c = ok ? a * wts[tp] : 0.f;
                csum += c;
                const float4* row = (const float4*)(src + (size_t)pix * 256);
                float4 v0 = __ldg(row + lane);
                float4 v1 = __ldg(row + 32 + lane);
                a0.x += c * v0.x; a0.y += c * v0.y; a0.z += c * v0.z; a0.w += c * v0.w;
                a1.x += c * v1.x; a1.y += c * v1.y; a1.z += c * v1.z; a1.w += c * v1.w;
            }
        }
    }
    float4* out = (float4*)(g_agg + (size_t)n * 2048 + h * 256);
    out[lane] = a0;
    out[32 + lane] = a1;
    if (lane == 0) g_csum[n * 8 + h] = csum;
}

// ================= per-head value projection =================
// out256[n, h*32+j] = valW_h row j . agg[n,h,:] + csum[n,h]*valb
__global__ __launch_bounds__(256) void k_headgemm(
    const float* __restrict__ valw, const float* __restrict__ valb)
{
    __shared__ float sw[32 * 258];
    int t = threadIdx.x;
    int h = blockIdx.y;
    int n0 = blockIdx.x * 64;
    for (int i = 0; i < 32; i++) {
        int idx = t + 256 * i;
        int r = idx >> 8, c = idx & 255;
        sw[r * 258 + c] = valw[(size_t)(h * 32 + r) * 256 + c];
    }
    __syncthreads();
    int j = t & 31, nb = t >> 5;
    float vb = valb[h * 32 + j];
#pragma unroll
    for (int i = 0; i < 8; i++) {
        int n = n0 + nb + 8 * i;
        const ull* ar2 = (const ull*)(g_agg + (size_t)n * 2048 + h * 256);
        ull acc2 = pack2(0.f, 0.f);
#pragma unroll 8
        for (int d2 = 0; d2 < 128; d2++) {
            ull w2 = *(const ull*)(sw + j * 258 + d2 * 2);
            fma2(acc2, __ldg(ar2 + d2), w2);
        }
        float2 r = unpack2(acc2);
        g_out256[(size_t)n * 256 + h * 32 + j] = r.x + r.y + g_csum[n * 8 + h] * vb;
    }
}

// ================= pooled mean + residual + norm1 =================
__global__ __launch_bounds__(256) void k_pool_ln(
    const float* __restrict__ n1w, const float* __restrict__ n1b)
{
    int e = blockIdx.x, t = threadIdx.x;
    float pooled = (g_ca[(3 * e + 0) * 256 + t] + g_ca[(3 * e + 1) * 256 + t] +
                    g_ca[(3 * e + 2) * 256 + t]) / 3.0f;
    float y = g_x[e * 256 + t] + pooled;
    g_x2[e * 256 + t] = block_ln256(y, n1w, n1b, t);
}

// ================= final residual + norm3 =================
__global__ __launch_bounds__(256) void k_final_ln(
    const float* __restrict__ n3w, const float* __restrict__ n3b,
    float* __restrict__ out)
{
    int e = blockIdx.x, t = threadIdx.x;
    float y = g_x2[e * 256 + t] + g_ffn[e * 256 + t];
    out[e * 256 + t] = block_ln256(y, n3w, n3b, t);
}

// ================= launch =================
extern "C" void kernel_launch(void* const* d_in, const int* in_sizes, int n_in,
                              void* d_out, int out_size) {
    const float* tgt      = (const float*)d_in[0];
    const float* qpos     = (const float*)d_in[1];
    const float* edge     = (const float*)d_in[2];
    const float* src      = (const float*)d_in[3];
    const unsigned char* msk = (const unsigned char*)d_in[4];
    const float* vr       = (const float*)d_in[5];
    const float* inw      = (const float*)d_in[6];
    const float* inb      = (const float*)d_in[7];
    const float* ow       = (const float*)d_in[8];
    const float* ob       = (const float*)d_in[9];
    const float* n1w      = (const float*)d_in[10];
    const float* n1b      = (const float*)d_in[11];
    const float* n2w      = (const float*)d_in[12];
    const float* n2b      = (const float*)d_in[13];
    const float* n3w      = (const float*)d_in[14];
    const float* n3b      = (const float*)d_in[15];
    const float* l0w      = (const float*)d_in[16];
    const float* l0b      = (const float*)d_in[17];
    const float* l1w      = (const float*)d_in[18];
    const float* l1b      = (const float*)d_in[19];
    const float* l2w      = (const float*)d_in[20];
    const float* l2b      = (const float*)d_in[21];
    const float* offw     = (const float*)d_in[22];
    const float* offb     = (const float*)d_in[23];
    const float* attww    = (const float*)d_in[24];
    const float* attwb    = (const float*)d_in[25];
    const float* valw     = (const float*)d_in[26];
    const float* valb     = (const float*)d_in[27];
    const float* oprojw   = (const float*)d_in[28];
    const float* oprojb   = (const float*)d_in[29];
    float* out = (float*)d_out;

    float *gqkout, *gx, *gnq, *goffatt, *gout256, *gca, *gx2, *ghid, *gffn;
    cudaGetSymbolAddress((void**)&gqkout, g_qkout);
    cudaGetSymbolAddress((void**)&gx, g_x);
    cudaGetSymbolAddress((void**)&gnq, g_nq);
    cudaGetSymbolAddress((void**)&goffatt, g_offatt);
    cudaGetSymbolAddress((void**)&gout256, g_out256);
    cudaGetSymbolAddress((void**)&gca, g_ca);
    cudaGetSymbolAddress((void**)&gx2, g_x2);
    cudaGetSymbolAddress((void**)&ghid, g_hid);
    cudaGetSymbolAddress((void**)&gffn, g_ffn);

    // geometry (independent)
    k_geom<<<3, 128>>>(edge);
    // fused QKV projection (q,k use tgt+qpos; v uses tgt)
    k_gemm2<<<dim3(12, 4), 256>>>(tgt, qpos, inw, nullptr, inb, nullptr,
                                  gqkout, 128, 768, 256, 0, 512, 1, 0);
    // self-attn + out-proj + norm2
    k_attn<<<128, 256>>>(ow, ob, tgt, n2w, n2b);
    // lin0 on [x+qpos | pe] (A composed on the fly)
    k_gemm2<<<dim3(4, 12), 256>>>(gx, qpos, l0w, nullptr, l0b, nullptr,
                                  gnq, 384, 256, 640, 0, 0, 2, 0);
    // fused offsets + attention-weight logits
    k_gemm2<<<dim3(6, 12), 256>>>(gnq, nullptr, offw, attww, offb, attwb,
                                  goffatt, 384, 384, 256, 256, 0, 0, 0);
    // deformable sampling (softmax + loc fused in)
    k_sample<<<384, 256>>>(src, msk, vr);
    // per-head value projection
    k_headgemm<<<dim3(6, 8), 256>>>(valw, valb);
    // output projection
    k_gemm2<<<dim3(4, 12), 256>>>(gout256, nullptr, oprojw, nullptr, oprojb, nullptr,
                                  gca, 384, 256, 256, 0, 0, 0, 0);
    // pool + norm1
    k_pool_ln<<<128, 256>>>(n1w, n1b);
    // FFN
    k_gemm2<<<dim3(16, 4), 256>>>(gx2, nullptr, l1w, nullptr, l1b, nullptr,
                                  ghid, 128, 1024, 256, 0, 0, 0, 1);
    k_gemm2<<<dim3(4, 4), 256>>>(ghid, nullptr, l2w, nullptr, l2b, nullptr,
                                 gffn, 128, 256, 1024, 0, 0, 0, 0);
    // final norm
    k_final_ln<<<128, 256>>>(n3w, n3b, out);
}